// round 3
// baseline (speedup 1.0000x reference)
#include <cuda_runtime.h>
#include <math.h>

#define MAXN 100000
typedef unsigned long long u64;

// ---------------- scratch (device globals) ----------------------------------
__device__ float g_yp[MAXN * 32];      // x @ W1p[0:64]
__device__ float g_yn[MAXN * 32];      // x @ W1n[0:64]
__device__ float g_sxp[MAXN * 32];     // x @ W1p[64:128] + b1p
__device__ float g_sxn[MAXN * 32];     // x @ W1n[64:128] + b1n
__device__ float g_apsum[MAXN * 32];   // seg_sum(yp, pos)
__device__ float g_ansum[MAXN * 32];   // seg_sum(yn, neg)
__device__ float g_cntp[MAXN];
__device__ float g_cntn[MAXN];
__device__ float g_zp[MAXN * 32];
__device__ float g_zn[MAXN * 32];
__device__ float g_szpp[MAXN * 32];    // seg_sum(zp, pos)
__device__ float g_sznp[MAXN * 32];    // seg_sum(zn, pos)
__device__ float g_sznn[MAXN * 32];    // seg_sum(zn, neg)
__device__ float g_szpn[MAXN * 32];    // seg_sum(zp, neg)
__device__ int   g_is64;

// ---------------- helpers ---------------------------------------------------
__device__ __forceinline__ void red_add_v4(float* addr, float4 v) {
    asm volatile("red.global.add.v4.f32 [%0], {%1, %2, %3, %4};"
                 :: "l"(addr), "f"(v.x), "f"(v.y), "f"(v.z), "f"(v.w)
                 : "memory");
}
__device__ __forceinline__ int load_idx(const void* ei, long long pos, int is64) {
    if (is64) return (int)__ldg((const long long*)ei + pos);
    return __ldg((const int*)ei + pos);
}
__device__ __forceinline__ u64 pack2(float s) {
    u64 r; asm("mov.b64 %0, {%1, %1};" : "=l"(r) : "f"(s)); return r;
}
__device__ __forceinline__ void fma2(u64& d, u64 a, u64 b) {
    asm("fma.rn.f32x2 %0, %1, %2, %0;" : "+l"(d) : "l"(a), "l"(b));
}
__device__ __forceinline__ float2 unpack2(u64 v) {
    float2 r; asm("mov.b64 {%0, %1}, %2;" : "=f"(r.x), "=f"(r.y) : "l"(v)); return r;
}
// acc[16] (f32x2 pairs, 32 cols) += s * W[k][0:32]   (W in shared)
__device__ __forceinline__ void row_fma(u64 acc[16], const float* Ws, int k, u64 ss) {
    const u64* w = (const u64*)(Ws + k * 32);
#pragma unroll
    for (int j = 0; j < 16; j++) fma2(acc[j], ss, w[j]);
}

// ---------------- dtype detection -------------------------------------------
__global__ void detect_dtype(const unsigned int* __restrict__ p) {
    int is64 = 1;
    for (int i = 1; i < 256; i += 2)
        if (p[i] != 0u) { is64 = 0; break; }
    g_is64 = is64;
}

// ---------------- projection + scratch zeroing -------------------------------
__global__ void project1(const float* __restrict__ x,
                         const float* __restrict__ W1p, const float* __restrict__ b1p,
                         const float* __restrict__ W1n, const float* __restrict__ b1n,
                         int n) {
    __shared__ float Wp[128 * 32];
    __shared__ float Wn[128 * 32];
    for (int t = threadIdx.x; t < 128 * 32; t += blockDim.x) { Wp[t] = W1p[t]; Wn[t] = W1n[t]; }
    __syncthreads();
    int i = blockIdx.x * blockDim.x + threadIdx.x;
    if (i >= n) return;
    const float4* x4 = (const float4*)x + (size_t)i * 16;

    // positive: yp = x@Wp[0:64], sxp = x@Wp[64:128] + b1p
    {
        u64 aY[16], aS[16];
#pragma unroll
        for (int j = 0; j < 16; j++) { aY[j] = 0ULL; aS[j] = 0ULL; }
#pragma unroll 4
        for (int kk = 0; kk < 16; kk++) {
            float4 v = x4[kk];
            int k = kk * 4;
            { u64 s = pack2(v.x); row_fma(aY, Wp, k + 0, s); row_fma(aS, Wp, 64 + k + 0, s); }
            { u64 s = pack2(v.y); row_fma(aY, Wp, k + 1, s); row_fma(aS, Wp, 64 + k + 1, s); }
            { u64 s = pack2(v.z); row_fma(aY, Wp, k + 2, s); row_fma(aS, Wp, 64 + k + 2, s); }
            { u64 s = pack2(v.w); row_fma(aY, Wp, k + 3, s); row_fma(aS, Wp, 64 + k + 3, s); }
        }
        u64* yo = (u64*)(g_yp + (size_t)i * 32);
        float2* so = (float2*)(g_sxp + (size_t)i * 32);
        const float2* bb = (const float2*)b1p;
#pragma unroll
        for (int j = 0; j < 16; j++) {
            yo[j] = aY[j];
            float2 f = unpack2(aS[j]); float2 b = __ldg(bb + j);
            so[j] = make_float2(f.x + b.x, f.y + b.y);
        }
    }
    // negative: yn = x@Wn[0:64], sxn = x@Wn[64:128] + b1n
    {
        u64 aY[16], aS[16];
#pragma unroll
        for (int j = 0; j < 16; j++) { aY[j] = 0ULL; aS[j] = 0ULL; }
#pragma unroll 4
        for (int kk = 0; kk < 16; kk++) {
            float4 v = x4[kk];
            int k = kk * 4;
            { u64 s = pack2(v.x); row_fma(aY, Wn, k + 0, s); row_fma(aS, Wn, 64 + k + 0, s); }
            { u64 s = pack2(v.y); row_fma(aY, Wn, k + 1, s); row_fma(aS, Wn, 64 + k + 1, s); }
            { u64 s = pack2(v.z); row_fma(aY, Wn, k + 2, s); row_fma(aS, Wn, 64 + k + 2, s); }
            { u64 s = pack2(v.w); row_fma(aY, Wn, k + 3, s); row_fma(aS, Wn, 64 + k + 3, s); }
        }
        u64* yo = (u64*)(g_yn + (size_t)i * 32);
        float2* so = (float2*)(g_sxn + (size_t)i * 32);
        const float2* bb = (const float2*)b1n;
#pragma unroll
        for (int j = 0; j < 16; j++) {
            yo[j] = aY[j];
            float2 f = unpack2(aS[j]); float2 b = __ldg(bb + j);
            so[j] = make_float2(f.x + b.x, f.y + b.y);
        }
    }
    // zero all scatter targets for this node (completes before edge kernels run)
    const float4 z4 = make_float4(0.f, 0.f, 0.f, 0.f);
    float4* a0 = (float4*)(g_apsum + (size_t)i * 32);
    float4* a1 = (float4*)(g_ansum + (size_t)i * 32);
    float4* a2 = (float4*)(g_szpp + (size_t)i * 32);
    float4* a3 = (float4*)(g_sznp + (size_t)i * 32);
    float4* a4p = (float4*)(g_sznn + (size_t)i * 32);
    float4* a5 = (float4*)(g_szpn + (size_t)i * 32);
#pragma unroll
    for (int q = 0; q < 8; q++) { a0[q] = z4; a1[q] = z4; a2[q] = z4; a3[q] = z4; a4p[q] = z4; a5[q] = z4; }
    g_cntp[i] = 0.f; g_cntn[i] = 0.f;
}

// ---------------- layer-1 edge scatter (projected, 32 feats) + counts -------
__global__ void edge1(const void* __restrict__ pe, const void* __restrict__ ne, int E) {
    const int is64 = g_is64;
    long long total = (long long)E * 16;  // 2E edges * 8 items
    long long stride = (long long)gridDim.x * blockDim.x;
    for (long long item = (long long)blockIdx.x * blockDim.x + threadIdx.x;
         item < total; item += stride) {
        long long e2 = item >> 3;
        int c = (int)(item & 7);
        bool pos = e2 < E;
        const void* ei = pos ? pe : ne;
        long long e = pos ? e2 : e2 - E;
        const float* y = pos ? g_yp : g_yn;
        float* sum = pos ? g_apsum : g_ansum;
        float* cnt = pos ? g_cntp : g_cntn;
        int s = load_idx(ei, e, is64);
        int d = load_idx(ei, (long long)E + e, is64);
        float4 v = __ldg((const float4*)y + (size_t)s * 8 + c);
        red_add_v4(sum + (size_t)d * 32 + c * 4, v);
        if (c == 0) atomicAdd(cnt + d, 1.0f);
    }
}

// ---------------- layer-1 activation: z = tanh(sum*inv + self) --------------
__global__ void node1b(int n) {
    int i = blockIdx.x * blockDim.x + threadIdx.x;
    if (i >= n) return;
    float invp = 1.f / fmaxf(g_cntp[i], 1.f);
    float invn = 1.f / fmaxf(g_cntn[i], 1.f);
    const float4* ap = (const float4*)(g_apsum + (size_t)i * 32);
    const float4* sp = (const float4*)(g_sxp + (size_t)i * 32);
    float4* zp = (float4*)(g_zp + (size_t)i * 32);
    const float4* an = (const float4*)(g_ansum + (size_t)i * 32);
    const float4* sn = (const float4*)(g_sxn + (size_t)i * 32);
    float4* zn = (float4*)(g_zn + (size_t)i * 32);
#pragma unroll
    for (int q = 0; q < 8; q++) {
        float4 a = ap[q], s = sp[q], o;
        o.x = tanhf(fmaf(a.x, invp, s.x));
        o.y = tanhf(fmaf(a.y, invp, s.y));
        o.z = tanhf(fmaf(a.z, invp, s.z));
        o.w = tanhf(fmaf(a.w, invp, s.w));
        zp[q] = o;
        a = an[q]; s = sn[q];
        o.x = tanhf(fmaf(a.x, invn, s.x));
        o.y = tanhf(fmaf(a.y, invn, s.y));
        o.z = tanhf(fmaf(a.z, invn, s.z));
        o.w = tanhf(fmaf(a.w, invn, s.w));
        zn[q] = o;
    }
}

// ---------------- layer-2 edge scatter: zp & zn in one pass, both lists -----
__global__ void edge2(const void* __restrict__ pe, const void* __restrict__ ne, int E) {
    const int is64 = g_is64;
    long long total = (long long)E * 32;  // 2E edges * 16 items
    long long stride = (long long)gridDim.x * blockDim.x;
    for (long long item = (long long)blockIdx.x * blockDim.x + threadIdx.x;
         item < total; item += stride) {
        long long e2 = item >> 4;
        int c = (int)(item & 15);
        bool pos = e2 < E;
        const void* ei = pos ? pe : ne;
        long long e = pos ? e2 : e2 - E;
        int s = load_idx(ei, e, is64);
        int d = load_idx(ei, (long long)E + e, is64);
        const float* za = pos ? g_zp : g_zn;
        const float* zb = pos ? g_zn : g_zp;
        float* sa = pos ? g_szpp : g_sznn;
        float* sb = pos ? g_sznp : g_szpn;
        if (c < 8) {
            float4 v = __ldg((const float4*)za + (size_t)s * 8 + c);
            red_add_v4(sa + (size_t)d * 32 + c * 4, v);
        } else {
            int cc = c - 8;
            float4 v = __ldg((const float4*)zb + (size_t)s * 8 + cc);
            red_add_v4(sb + (size_t)d * 32 + cc * 4, v);
        }
    }
}

// ---------------- layer-2 node update -> output ------------------------------
__global__ void node_l2(const float* __restrict__ W2p, const float* __restrict__ b2p,
                        const float* __restrict__ W2n, const float* __restrict__ b2n,
                        float* __restrict__ out, int n) {
    __shared__ float Wp[96 * 32];
    __shared__ float Wn[96 * 32];
    for (int t = threadIdx.x; t < 96 * 32; t += blockDim.x) { Wp[t] = W2p[t]; Wn[t] = W2n[t]; }
    __syncthreads();
    int i = blockIdx.x * blockDim.x + threadIdx.x;
    if (i >= n) return;
    float invp = 1.f / fmaxf(g_cntp[i], 1.f);
    float invn = 1.f / fmaxf(g_cntn[i], 1.f);

    // positive: [szpp*invp, sznn*invn, zp] @ W2p + b2p
    {
        u64 acc[16];
#pragma unroll
        for (int j = 0; j < 16; j++) acc[j] = 0ULL;
        const float4* s0 = (const float4*)(g_szpp + (size_t)i * 32);
        const float4* s1 = (const float4*)(g_sznn + (size_t)i * 32);
        const float4* s2 = (const float4*)(g_zp + (size_t)i * 32);
#pragma unroll 4
        for (int kk = 0; kk < 8; kk++) {
            float4 v = s0[kk]; int k = kk * 4;
            row_fma(acc, Wp, k + 0, pack2(v.x * invp));
            row_fma(acc, Wp, k + 1, pack2(v.y * invp));
            row_fma(acc, Wp, k + 2, pack2(v.z * invp));
            row_fma(acc, Wp, k + 3, pack2(v.w * invp));
        }
#pragma unroll 4
        for (int kk = 0; kk < 8; kk++) {
            float4 v = s1[kk]; int k = 32 + kk * 4;
            row_fma(acc, Wp, k + 0, pack2(v.x * invn));
            row_fma(acc, Wp, k + 1, pack2(v.y * invn));
            row_fma(acc, Wp, k + 2, pack2(v.z * invn));
            row_fma(acc, Wp, k + 3, pack2(v.w * invn));
        }
#pragma unroll 4
        for (int kk = 0; kk < 8; kk++) {
            float4 v = s2[kk]; int k = 64 + kk * 4;
            row_fma(acc, Wp, k + 0, pack2(v.x));
            row_fma(acc, Wp, k + 1, pack2(v.y));
            row_fma(acc, Wp, k + 2, pack2(v.z));
            row_fma(acc, Wp, k + 3, pack2(v.w));
        }
        const float2* bb = (const float2*)b2p;
        float2* o2 = (float2*)(out + (size_t)i * 64);
#pragma unroll
        for (int j = 0; j < 16; j++) {
            float2 f = unpack2(acc[j]); float2 b = __ldg(bb + j);
            o2[j] = make_float2(tanhf(f.x + b.x), tanhf(f.y + b.y));
        }
    }
    // negative: [sznp*invp, szpn*invn, zn] @ W2n + b2n
    {
        u64 acc[16];
#pragma unroll
        for (int j = 0; j < 16; j++) acc[j] = 0ULL;
        const float4* s0 = (const float4*)(g_sznp + (size_t)i * 32);
        const float4* s1 = (const float4*)(g_szpn + (size_t)i * 32);
        const float4* s2 = (const float4*)(g_zn + (size_t)i * 32);
#pragma unroll 4
        for (int kk = 0; kk < 8; kk++) {
            float4 v = s0[kk]; int k = kk * 4;
            row_fma(acc, Wn, k + 0, pack2(v.x * invp));
            row_fma(acc, Wn, k + 1, pack2(v.y * invp));
            row_fma(acc, Wn, k + 2, pack2(v.z * invp));
            row_fma(acc, Wn, k + 3, pack2(v.w * invp));
        }
#pragma unroll 4
        for (int kk = 0; kk < 8; kk++) {
            float4 v = s1[kk]; int k = 32 + kk * 4;
            row_fma(acc, Wn, k + 0, pack2(v.x * invn));
            row_fma(acc, Wn, k + 1, pack2(v.y * invn));
            row_fma(acc, Wn, k + 2, pack2(v.z * invn));
            row_fma(acc, Wn, k + 3, pack2(v.w * invn));
        }
#pragma unroll 4
        for (int kk = 0; kk < 8; kk++) {
            float4 v = s2[kk]; int k = 64 + kk * 4;
            row_fma(acc, Wn, k + 0, pack2(v.x));
            row_fma(acc, Wn, k + 1, pack2(v.y));
            row_fma(acc, Wn, k + 2, pack2(v.z));
            row_fma(acc, Wn, k + 3, pack2(v.w));
        }
        const float2* bb = (const float2*)b2n;
        float2* o2 = (float2*)(out + (size_t)i * 64 + 32);
#pragma unroll
        for (int j = 0; j < 16; j++) {
            float2 f = unpack2(acc[j]); float2 b = __ldg(bb + j);
            o2[j] = make_float2(tanhf(f.x + b.x), tanhf(f.y + b.y));
        }
    }
}

// ---------------- launch ------------------------------------------------------
extern "C" void kernel_launch(void* const* d_in, const int* in_sizes, int n_in,
                              void* d_out, int out_size) {
    const float* x   = (const float*)d_in[0];
    const float* W1p = (const float*)d_in[1];
    const float* b1p = (const float*)d_in[2];
    const float* W1n = (const float*)d_in[3];
    const float* b1n = (const float*)d_in[4];
    const float* W2p = (const float*)d_in[5];
    const float* b2p = (const float*)d_in[6];
    const float* W2n = (const float*)d_in[7];
    const float* b2n = (const float*)d_in[8];
    const void* pe = d_in[9];
    const void* ne = d_in[10];

    int n = in_sizes[0] / 64;
    int E = in_sizes[9] / 2;
    float* out = (float*)d_out;

    detect_dtype<<<1, 1>>>((const unsigned int*)pe);
    project1<<<(n + 255) / 256, 256>>>(x, W1p, b1p, W1n, b1n, n);
    edge1<<<4736, 256>>>(pe, ne, E);
    node1b<<<(n + 255) / 256, 256>>>(n);
    edge2<<<4736, 256>>>(pe, ne, E);
    node_l2<<<(n + 255) / 256, 256>>>(W2p, b2p, W2n, b2n, out, n);
}